// round 1
// baseline (speedup 1.0000x reference)
#include <cuda_runtime.h>

// Problem constants (STGNN_91242285236402): B=8, T=16, N=64, F=16, H=128
#define Bc 8
#define Tc 16
#define Nc 64
#define Fc 16
#define Hc 128
#define BN (Bc * Nc)   // 512 rows

// Scratch (allocation-free: __device__ globals)
__device__ float g_a [BN * Hc];   // node @ W1s.T + b1
__device__ float g_bt[BN * Hc];   // node @ W1t.T
__device__ float g_lp[BN];        // dot(lin[b,n,:], Wp) folded scalar
__device__ float g_wvec[Hc];      // Wgcn.T @ Wp
__device__ float g_cb;            // dot(Wp, bgcn)

// ---------------------------------------------------------------------------
// K_pre: wvec[h] = sum_k Wp[k]*Wgcn[k,h];  cb = sum_k Wp[k]*bgcn[k];
//        init pressures region of d_out to bp.
// 1 block, 128 threads.
// ---------------------------------------------------------------------------
__global__ void kpre(const float* __restrict__ Wp,
                     const float* __restrict__ Wgcn,
                     const float* __restrict__ bgcn,
                     const float* __restrict__ bp,
                     float* __restrict__ out)
{
    int t = threadIdx.x;  // 0..127
    float s = 0.f;
    #pragma unroll 8
    for (int k = 0; k < Hc; k++)
        s += Wp[k] * Wgcn[k * Hc + t];
    g_wvec[t] = s;

    __shared__ float red[Hc];
    red[t] = Wp[t] * bgcn[t];
    __syncthreads();
    for (int off = 64; off; off >>= 1) {
        if (t < off) red[t] += red[t + off];
        __syncthreads();
    }
    if (t == 0) g_cb = red[0];

    float bpv = bp[0];
    for (int i = t; i < BN; i += 128) out[i] = bpv;
}

// ---------------------------------------------------------------------------
// K0: per node-row (b,n) at t = T-1:
//   node[h] = bg[h] + sum_f x[b,T-1,n,f] * Wg[h,f]
//   a[k]  = b1[k] + sum_h node[h] * W1[k, h]        (W1s half)
//   bt[k] =         sum_h node[h] * W1[k, 128+h]    (W1t half)
//   lp    = cb + sum_h node[h] * wvec[h]
// 128 blocks x 256 threads; 4 rows per block; tid>>7 selects a vs bt.
// ---------------------------------------------------------------------------
__global__ void k0(const float* __restrict__ x,
                   const float* __restrict__ Wg,
                   const float* __restrict__ bg,
                   const float* __restrict__ W1,
                   const float* __restrict__ b1)
{
    __shared__ float x_sh[4][Fc];
    __shared__ float node_sh[4][Hc];
    __shared__ float wvec_sh[Hc];

    const int tid = threadIdx.x;          // 0..255
    const int rowbase = blockIdx.x * 4;   // global row = b*N + n

    if (tid < 4 * Fc) {
        int r = tid >> 4, f = tid & (Fc - 1);
        int row = rowbase + r;
        int b = row >> 6, n = row & (Nc - 1);
        // x[b, T-1, n, f]
        x_sh[r][f] = x[(((b * Tc + (Tc - 1)) * Nc + n) * Fc) + f];
    }
    if (tid >= 128) wvec_sh[tid - 128] = g_wvec[tid - 128];
    __syncthreads();

    // node: 4 rows x 128 h = 512 outputs over 256 threads
    #pragma unroll
    for (int idx = tid; idx < 4 * Hc; idx += 256) {
        int r = idx >> 7, h = idx & (Hc - 1);
        float s = bg[h];
        #pragma unroll
        for (int f = 0; f < Fc; f++)
            s += x_sh[r][f] * __ldg(&Wg[h * Fc + f]);
        node_sh[r][h] = s;
    }
    __syncthreads();

    const int k   = tid & 127;
    const int sel = tid >> 7;      // 0 -> a (W1s), 1 -> bt (W1t)
    const float* wrow = W1 + k * (2 * Hc) + sel * Hc;

    float acc0 = 0.f, acc1 = 0.f, acc2 = 0.f, acc3 = 0.f;
    #pragma unroll 8
    for (int h = 0; h < Hc; h++) {
        float w = __ldg(&wrow[h]);
        acc0 += node_sh[0][h] * w;
        acc1 += node_sh[1][h] * w;
        acc2 += node_sh[2][h] * w;
        acc3 += node_sh[3][h] * w;
    }
    float bias = sel ? 0.f : __ldg(&b1[k]);
    float* dst = sel ? g_bt : g_a;
    dst[(rowbase + 0) * Hc + k] = acc0 + bias;
    dst[(rowbase + 1) * Hc + k] = acc1 + bias;
    dst[(rowbase + 2) * Hc + k] = acc2 + bias;
    dst[(rowbase + 3) * Hc + k] = acc3 + bias;

    // lp: warp w (0..3) reduces row w
    if (tid < 128) {
        int w = tid >> 5, l = tid & 31;
        float s = 0.f;
        #pragma unroll
        for (int j = 0; j < 4; j++) {
            int h = l + 32 * j;
            s += node_sh[w][h] * wvec_sh[h];
        }
        #pragma unroll
        for (int o = 16; o; o >>= 1) s += __shfl_xor_sync(0xffffffffu, s, o);
        if (l == 0) g_lp[rowbase + w] = s + g_cb;
    }
}

// ---------------------------------------------------------------------------
// K1: one warp per (b, edge):
//   ew = b2 + sum_k relu(a[b,src,k] + bt[b,tgt,k]) * W2[k]
//   out_ew[b*E+e] = ew
//   atomicAdd(pressures[b*N+tgt], ew * lp[b*N+src])
// ---------------------------------------------------------------------------
__global__ void k1(const int* __restrict__ ei,
                   const float* __restrict__ W2,
                   const float* __restrict__ b2,
                   float* __restrict__ out,
                   int E)
{
    const int warp = (blockIdx.x * blockDim.x + threadIdx.x) >> 5;
    const int lane = threadIdx.x & 31;
    if (warp >= Bc * E) return;

    const int b = warp / E;
    const int e = warp - b * E;
    const int src = ei[e];
    const int tgt = ei[E + e];

    const float4 av = *((const float4*)(g_a  + (b * Nc + src) * Hc) + lane);
    const float4 tv = *((const float4*)(g_bt + (b * Nc + tgt) * Hc) + lane);
    const float4 w2 = __ldg((const float4*)W2 + lane);

    float acc = fmaxf(av.x + tv.x, 0.f) * w2.x
              + fmaxf(av.y + tv.y, 0.f) * w2.y
              + fmaxf(av.z + tv.z, 0.f) * w2.z
              + fmaxf(av.w + tv.w, 0.f) * w2.w;
    #pragma unroll
    for (int o = 16; o; o >>= 1) acc += __shfl_xor_sync(0xffffffffu, acc, o);

    if (lane == 0) {
        float ew = acc + __ldg(b2);
        out[BN + b * E + e] = ew;                       // ew[:, -1]
        atomicAdd(out + b * Nc + tgt, ew * g_lp[b * Nc + src]);  // pressures
    }
}

// ---------------------------------------------------------------------------
// Inputs (metadata order):
//  0 x_seq (B,T,N,F) f32      1 edge_index (2,E) i32   2 Wg (H,F)
//  3 bg (H)                   4 W1 (H,2H)              5 b1 (H)
//  6 W2 (1,H)                 7 b2 (1)                 8 Wgcn (H,H)
//  9 bgcn (H)                10 Wih                   11 Whh
// 12 bih                     13 bhh                   14 Wp (1,H)
// 15 bp (1)
// Output: pressures (B,N) then ew_last (B,E), concatenated fp32.
// ---------------------------------------------------------------------------
extern "C" void kernel_launch(void* const* d_in, const int* in_sizes, int n_in,
                              void* d_out, int out_size)
{
    const float* x    = (const float*)d_in[0];
    const int*   ei   = (const int*)  d_in[1];
    const float* Wg   = (const float*)d_in[2];
    const float* bg   = (const float*)d_in[3];
    const float* W1   = (const float*)d_in[4];
    const float* b1   = (const float*)d_in[5];
    const float* W2   = (const float*)d_in[6];
    const float* b2   = (const float*)d_in[7];
    const float* Wgcn = (const float*)d_in[8];
    const float* bgcn = (const float*)d_in[9];
    const float* Wp   = (const float*)d_in[14];
    const float* bp   = (const float*)d_in[15];
    float* out = (float*)d_out;

    const int E = in_sizes[1] / 2;   // 4032

    kpre<<<1, 128>>>(Wp, Wgcn, bgcn, bp, out);
    k0<<<BN / 4, 256>>>(x, Wg, bg, W1, b1);
    const int warps = Bc * E;                 // 32256
    const int blocks = (warps + 7) / 8;       // 8 warps (256 thr) per block
    k1<<<blocks, 256>>>(ei, W2, b2, out, E);
}

// round 2
// speedup vs baseline: 1.0617x; 1.0617x over previous
#include <cuda_runtime.h>

// Problem constants (STGNN_91242285236402): B=8, T=16, N=64, F=16, H=128
#define Bc 8
#define Tc 16
#define Nc 64
#define Fc 16
#define Hc 128
#define BN (Bc * Nc)   // 512 rows
#define ROWS_PER_BLK 8

// Scratch (allocation-free: __device__ globals)
__device__ float g_a [BN * Hc];   // node @ W1s.T + b1
__device__ float g_bt[BN * Hc];   // node @ W1t.T
__device__ float g_lp[BN];        // Wp . (Wgcn@node + bgcn) folded scalar

// ---------------------------------------------------------------------------
// kA: per block handles 8 node-rows (b,n) at t = T-1.
//   wvec[h] = sum_k Wp[k]*Wgcn[k,h]   (redundant per block, coalesced)
//   cb      = sum_k Wp[k]*bgcn[k]
//   node[h] = bg[h] + sum_f x[b,T-1,n,f] * Wg[h,f]
//   a[k]  = b1[k] + sum_h node[h] * W1[k, h]
//   bt[k] =         sum_h node[h] * W1[k, 128+h]
//   lp    = cb + sum_h node[h] * wvec[h]
//   out[row] = bp   (init pressures for k1's atomics)
// 64 blocks x 256 threads.
// ---------------------------------------------------------------------------
__global__ void kA(const float* __restrict__ x,
                   const float* __restrict__ Wg,
                   const float* __restrict__ bg,
                   const float* __restrict__ W1,
                   const float* __restrict__ b1,
                   const float* __restrict__ Wgcn,
                   const float* __restrict__ bgcn,
                   const float* __restrict__ Wp,
                   const float* __restrict__ bp,
                   float* __restrict__ out)
{
    __shared__ float x_sh[ROWS_PER_BLK][Fc];
    __shared__ float node_sh[ROWS_PER_BLK][Hc];
    __shared__ float wv2[2][Hc];
    __shared__ float cb_sh;

    const int tid = threadIdx.x;              // 0..255
    const int rowbase = blockIdx.x * ROWS_PER_BLK;
    const int t    = tid & (Hc - 1);          // 0..127
    const int half = tid >> 7;                // 0/1

    // ---- x staging (8 rows x 16 f = 128 floats) + pressures init ----
    if (tid < ROWS_PER_BLK * Fc) {
        int r = tid >> 4, f = tid & (Fc - 1);
        int row = rowbase + r;
        int b = row >> 6, n = row & (Nc - 1);
        x_sh[r][f] = x[(((b * Tc + (Tc - 1)) * Nc + n) * Fc) + f];
    }
    if (tid < ROWS_PER_BLK) out[rowbase + tid] = bp[0];

    // ---- wvec: thread (t,half) sums 64 k's, coalesced across t ----
    {
        float s = 0.f;
        const int k0 = half * 64;
        #pragma unroll 16
        for (int k = 0; k < 64; k++)
            s += Wp[k0 + k] * Wgcn[(k0 + k) * Hc + t];
        wv2[half][t] = s;
    }

    // ---- cb: first 4 warps reduce Wp[t]*bgcn[t] ----
    if (tid == 0) cb_sh = 0.f;
    __syncthreads();
    if (tid < Hc) {
        float v = Wp[t] * bgcn[t];
        #pragma unroll
        for (int o = 16; o; o >>= 1) v += __shfl_xor_sync(0xffffffffu, v, o);
        if ((tid & 31) == 0) atomicAdd(&cb_sh, v);
    }

    // ---- node: 8 rows x 128 h = 1024 outputs over 256 threads ----
    #pragma unroll
    for (int i = 0; i < ROWS_PER_BLK * Hc / 256; i++) {
        int idx = tid + i * 256;
        int r = idx >> 7, h = idx & (Hc - 1);
        float s = bg[h];
        #pragma unroll
        for (int f = 0; f < Fc; f++)
            s += x_sh[r][f] * __ldg(&Wg[h * Fc + f]);
        node_sh[r][h] = s;
    }
    __syncthreads();

    // ---- a / bt: thread -> (k = t, sel = half), 8 accumulators ----
    {
        const float* wrow = W1 + t * (2 * Hc) + half * Hc;
        float acc[ROWS_PER_BLK];
        #pragma unroll
        for (int r = 0; r < ROWS_PER_BLK; r++) acc[r] = 0.f;
        #pragma unroll 8
        for (int h = 0; h < Hc; h++) {
            float w = __ldg(&wrow[h]);
            #pragma unroll
            for (int r = 0; r < ROWS_PER_BLK; r++)
                acc[r] += node_sh[r][h] * w;
        }
        float bias = half ? 0.f : __ldg(&b1[t]);
        float* dst = half ? g_bt : g_a;
        #pragma unroll
        for (int r = 0; r < ROWS_PER_BLK; r++)
            dst[(rowbase + r) * Hc + t] = acc[r] + bias;
    }

    // ---- lp: warp w (0..7) reduces row w ----
    {
        int w = tid >> 5, l = tid & 31;
        float s = 0.f;
        #pragma unroll
        for (int j = 0; j < 4; j++) {
            int h = l + 32 * j;
            s += node_sh[w][h] * (wv2[0][h] + wv2[1][h]);
        }
        #pragma unroll
        for (int o = 16; o; o >>= 1) s += __shfl_xor_sync(0xffffffffu, s, o);
        if (l == 0) g_lp[rowbase + w] = s + cb_sh;
    }
}

// ---------------------------------------------------------------------------
// k1: one warp per (b, edge):
//   ew = b2 + sum_k relu(a[b,src,k] + bt[b,tgt,k]) * W2[k]
//   out_ew[b*E+e] = ew
//   atomicAdd(pressures[b*N+tgt], ew * lp[b*N+src])
// ---------------------------------------------------------------------------
__global__ void k1(const int* __restrict__ ei,
                   const float* __restrict__ W2,
                   const float* __restrict__ b2,
                   float* __restrict__ out,
                   int E)
{
    const int warp = (blockIdx.x * blockDim.x + threadIdx.x) >> 5;
    const int lane = threadIdx.x & 31;
    if (warp >= Bc * E) return;

    const int b = warp / E;
    const int e = warp - b * E;
    const int src = ei[e];
    const int tgt = ei[E + e];

    const float4 av = *((const float4*)(g_a  + (b * Nc + src) * Hc) + lane);
    const float4 tv = *((const float4*)(g_bt + (b * Nc + tgt) * Hc) + lane);
    const float4 w2 = __ldg((const float4*)W2 + lane);

    float acc = fmaxf(av.x + tv.x, 0.f) * w2.x
              + fmaxf(av.y + tv.y, 0.f) * w2.y
              + fmaxf(av.z + tv.z, 0.f) * w2.z
              + fmaxf(av.w + tv.w, 0.f) * w2.w;
    #pragma unroll
    for (int o = 16; o; o >>= 1) acc += __shfl_xor_sync(0xffffffffu, acc, o);

    if (lane == 0) {
        float ew = acc + __ldg(b2);
        out[BN + b * E + e] = ew;                                // ew[:, -1]
        atomicAdd(out + b * Nc + tgt, ew * g_lp[b * Nc + src]);  // pressures
    }
}

// ---------------------------------------------------------------------------
// Inputs (metadata order):
//  0 x_seq (B,T,N,F) f32      1 edge_index (2,E) i32   2 Wg (H,F)
//  3 bg (H)                   4 W1 (H,2H)              5 b1 (H)
//  6 W2 (1,H)                 7 b2 (1)                 8 Wgcn (H,H)
//  9 bgcn (H)                10 Wih                   11 Whh
// 12 bih                     13 bhh                   14 Wp (1,H)
// 15 bp (1)
// Output: pressures (B,N) then ew_last (B,E), concatenated fp32.
// ---------------------------------------------------------------------------
extern "C" void kernel_launch(void* const* d_in, const int* in_sizes, int n_in,
                              void* d_out, int out_size)
{
    const float* x    = (const float*)d_in[0];
    const int*   ei   = (const int*)  d_in[1];
    const float* Wg   = (const float*)d_in[2];
    const float* bg   = (const float*)d_in[3];
    const float* W1   = (const float*)d_in[4];
    const float* b1   = (const float*)d_in[5];
    const float* W2   = (const float*)d_in[6];
    const float* b2   = (const float*)d_in[7];
    const float* Wgcn = (const float*)d_in[8];
    const float* bgcn = (const float*)d_in[9];
    const float* Wp   = (const float*)d_in[14];
    const float* bp   = (const float*)d_in[15];
    float* out = (float*)d_out;

    const int E = in_sizes[1] / 2;   // 4032

    kA<<<BN / ROWS_PER_BLK, 256>>>(x, Wg, bg, W1, b1, Wgcn, bgcn, Wp, bp, out);

    const int warps  = Bc * E;                  // 32256
    const int blocks = (warps + 15) / 16;       // 16 warps (512 thr) per block
    k1<<<blocks, 512>>>(ei, W2, b2, out, E);
}

// round 3
// speedup vs baseline: 1.7232x; 1.6231x over previous
#include <cuda_runtime.h>

// Problem constants (STGNN_91242285236402): B=8, T=16, N=64, F=16, H=128
#define Bc 8
#define Tc 16
#define Nc 64
#define Fc 16
#define Hc 128
#define BN (Bc * Nc)   // 512
#define PADN 68        // padded row width for bt_sh [k][t]

// Scratch (allocation-free: __device__ globals)
__device__ float g_a  [BN * Hc];        // a[row][k]   = node@W1s.T + b1
__device__ float g_btT[Bc * Hc * Nc];   // btT[b][k][n] = (node@W1t.T) transposed
__device__ float g_lp [BN];             // Wp . (Wgcn@node + bgcn)

// ---------------------------------------------------------------------------
// kA: 64 blocks x 256 threads, block handles 8 node-rows at t = T-1.
//  node[h] = bg[h] + sum_f x*Wg ;  a[k] = b1[k]+node.W1s[k] ; btT = node.W1t[k]
//  lp = cb + node.wvec ; out[row] = bp
//  GEMM: 8-lane sub-warp dots, coalesced W1 row reads, node cached in regs.
// ---------------------------------------------------------------------------
__global__ void __launch_bounds__(256) kA(
    const float* __restrict__ x,   const float* __restrict__ Wg,
    const float* __restrict__ bg,  const float* __restrict__ W1,
    const float* __restrict__ b1,  const float* __restrict__ Wgcn,
    const float* __restrict__ bgcn,const float* __restrict__ Wp,
    const float* __restrict__ bp,  float* __restrict__ out)
{
    __shared__ float x_sh[8][Fc];
    __shared__ float node_sh[8][Hc];
    __shared__ float wv2[2][Hc];
    __shared__ float cb_sh;

    const int tid = threadIdx.x;
    const int rowbase = blockIdx.x * 8;
    const int t    = tid & (Hc - 1);
    const int half = tid >> 7;

    // stage x (8 rows x 16 f) + pressures init
    if (tid < 128) {
        int r = tid >> 4, f = tid & 15;
        int row = rowbase + r, b = row >> 6, n = row & 63;
        x_sh[r][f] = x[(((b * Tc + (Tc - 1)) * Nc + n) * Fc) + f];
    }
    if (tid < 8) out[rowbase + tid] = __ldg(bp);

    // wvec halves: coalesced Wgcn rows
    {
        float s = 0.f;
        const int k0 = half * 64;
        #pragma unroll 16
        for (int k = 0; k < 64; k++)
            s += __ldg(&Wp[k0 + k]) * __ldg(&Wgcn[(k0 + k) * Hc + t]);
        wv2[half][t] = s;
    }
    if (tid == 0) cb_sh = 0.f;
    __syncthreads();

    if (tid < 128) {
        float v = __ldg(&Wp[t]) * __ldg(&bgcn[t]);
        #pragma unroll
        for (int o = 16; o; o >>= 1) v += __shfl_xor_sync(0xffffffffu, v, o);
        if ((tid & 31) == 0) atomicAdd(&cb_sh, v);
    }

    // node: 1024 values over 256 threads
    #pragma unroll
    for (int i = 0; i < 4; i++) {
        int idx = tid + i * 256;
        int r = idx >> 7, h = idx & 127;
        const float4* wg4 = (const float4*)(Wg + h * Fc);
        float4 w0 = __ldg(wg4 + 0), w1 = __ldg(wg4 + 1);
        float4 w2 = __ldg(wg4 + 2), w3 = __ldg(wg4 + 3);
        float acc = __ldg(&bg[h]);
        acc += x_sh[r][0]*w0.x + x_sh[r][1]*w0.y + x_sh[r][2]*w0.z + x_sh[r][3]*w0.w;
        acc += x_sh[r][4]*w1.x + x_sh[r][5]*w1.y + x_sh[r][6]*w1.z + x_sh[r][7]*w1.w;
        acc += x_sh[r][8]*w2.x + x_sh[r][9]*w2.y + x_sh[r][10]*w2.z + x_sh[r][11]*w2.w;
        acc += x_sh[r][12]*w3.x + x_sh[r][13]*w3.y + x_sh[r][14]*w3.z + x_sh[r][15]*w3.w;
        node_sh[r][h] = acc;
    }
    __syncthreads();

    const int lane = tid & 31, w = tid >> 5;
    const int j = lane & 7, d = lane >> 3;       // 8-lane dot groups, 4 dots/warp
    const int half2 = w >> 2;                    // 0: a, 1: btT
    const int kbase = (w & 3) * 32;

    #pragma unroll
    for (int r = 0; r < 8; r++) {
        const float* nrow = &node_sh[r][j * 16];
        float4 n0 = *(const float4*)(nrow + 0);
        float4 n1 = *(const float4*)(nrow + 4);
        float4 n2 = *(const float4*)(nrow + 8);
        float4 n3 = *(const float4*)(nrow + 12);
        #pragma unroll
        for (int kk = 0; kk < 8; kk++) {
            int k = kbase + kk * 4 + d;
            const float4* wp4 = (const float4*)(W1 + k * (2 * Hc) + half2 * Hc + j * 16);
            float4 w0 = __ldg(wp4 + 0), w1 = __ldg(wp4 + 1);
            float4 w2 = __ldg(wp4 + 2), w3 = __ldg(wp4 + 3);
            float acc = n0.x*w0.x + n0.y*w0.y + n0.z*w0.z + n0.w*w0.w
                      + n1.x*w1.x + n1.y*w1.y + n1.z*w1.z + n1.w*w1.w
                      + n2.x*w2.x + n2.y*w2.y + n2.z*w2.z + n2.w*w2.w
                      + n3.x*w3.x + n3.y*w3.y + n3.z*w3.z + n3.w*w3.w;
            acc += __shfl_xor_sync(0xffffffffu, acc, 1);
            acc += __shfl_xor_sync(0xffffffffu, acc, 2);
            acc += __shfl_xor_sync(0xffffffffu, acc, 4);
            if (j == 0) {
                int row = rowbase + r;
                if (half2 == 0) {
                    g_a[row * Hc + k] = acc + __ldg(&b1[k]);
                } else {
                    int b = row >> 6, n = row & 63;
                    g_btT[(b * Hc + k) * Nc + n] = acc;
                }
            }
        }
    }

    // lp: warp w reduces row w
    {
        float4 n  = *(const float4*)&node_sh[w][lane * 4];
        float4 wa = *(const float4*)&wv2[0][lane * 4];
        float4 wb = *(const float4*)&wv2[1][lane * 4];
        float v = n.x*(wa.x+wb.x) + n.y*(wa.y+wb.y) + n.z*(wa.z+wb.z) + n.w*(wa.w+wb.w);
        #pragma unroll
        for (int o = 16; o; o >>= 1) v += __shfl_xor_sync(0xffffffffu, v, o);
        if (lane == 0) g_lp[rowbase + w] = v + cb_sh;
    }
}

// ---------------------------------------------------------------------------
// k1 (dense): 128 blocks x 256 threads. Block = (b, src-group of 4).
// Warp = (src_local, tgt-half); lane = tgt. One 128-k loop computes 32 edges.
//   ew(s,t) = b2 + sum_k relu(a[s,k] + btT[k,t]) * W2[k]
//   pressures[b,t] += ew * lp[s]   (dense over all ordered pairs s != t)
//   e = s*63 + (t - (t>s))   [itertools.permutations order]
// ---------------------------------------------------------------------------
__global__ void __launch_bounds__(256) k1(
    const float* __restrict__ W2, const float* __restrict__ b2,
    float* __restrict__ out, int E)
{
    __shared__ float bt_sh[Hc][PADN];   // transposed, conflict-free reads
    __shared__ float a_sh[4][Hc];
    __shared__ float w2_sh[Hc];
    __shared__ float lp_sh[4];
    __shared__ float pr_sh[Nc];

    const int tid = threadIdx.x;
    const int b = blockIdx.x >> 4;
    const int g = blockIdx.x & 15;

    // stage btT[b] (128 x 64 floats)
    const float4* src4 = (const float4*)(g_btT + b * Hc * Nc);
    #pragma unroll
    for (int p = 0; p < 8; p++) {
        int q = tid + p * 256;          // quad index 0..2047
        int k = q >> 4, t4 = q & 15;
        float4 v = __ldg(src4 + q);
        *(float4*)&bt_sh[k][t4 * 4] = v;
    }
    if (tid < 128) {
        int sl = tid >> 5, k4 = tid & 31;
        *(float4*)&a_sh[sl][k4 * 4] =
            __ldg((const float4*)(g_a + (b * Nc + g * 4 + sl) * Hc) + k4);
        w2_sh[tid] = __ldg(&W2[tid]);
    }
    if (tid < 4)  lp_sh[tid] = g_lp[b * Nc + g * 4 + tid];
    if (tid < Nc) pr_sh[tid] = 0.f;
    __syncthreads();

    const int w = tid >> 5, lane = tid & 31;
    const int sl = w >> 1;                 // 0..3
    const int t  = (w & 1) * 32 + lane;    // 0..63
    const int s  = g * 4 + sl;             // 0..63

    float acc = 0.f;
    #pragma unroll 8
    for (int kq = 0; kq < 32; kq++) {
        float4 a4 = *(const float4*)&a_sh[sl][kq * 4];   // broadcast
        float4 w4 = *(const float4*)&w2_sh[kq * 4];      // broadcast
        float b0 = bt_sh[kq * 4 + 0][t];
        float b1 = bt_sh[kq * 4 + 1][t];
        float b2v= bt_sh[kq * 4 + 2][t];
        float b3 = bt_sh[kq * 4 + 3][t];
        acc += fmaxf(a4.x + b0, 0.f) * w4.x;
        acc += fmaxf(a4.y + b1, 0.f) * w4.y;
        acc += fmaxf(a4.z + b2v,0.f) * w4.z;
        acc += fmaxf(a4.w + b3, 0.f) * w4.w;
    }

    if (t != s) {
        float ew = acc + __ldg(b2);
        int e = s * 63 + (t < s ? t : t - 1);
        out[BN + b * E + e] = ew;
        atomicAdd(&pr_sh[t], ew * lp_sh[sl]);
    }
    __syncthreads();
    if (tid < Nc) atomicAdd(out + b * Nc + tid, pr_sh[tid]);
}

// ---------------------------------------------------------------------------
extern "C" void kernel_launch(void* const* d_in, const int* in_sizes, int n_in,
                              void* d_out, int out_size)
{
    const float* x    = (const float*)d_in[0];
    const float* Wg   = (const float*)d_in[2];
    const float* bg   = (const float*)d_in[3];
    const float* W1   = (const float*)d_in[4];
    const float* b1   = (const float*)d_in[5];
    const float* W2   = (const float*)d_in[6];
    const float* b2   = (const float*)d_in[7];
    const float* Wgcn = (const float*)d_in[8];
    const float* bgcn = (const float*)d_in[9];
    const float* Wp   = (const float*)d_in[14];
    const float* bp   = (const float*)d_in[15];
    float* out = (float*)d_out;

    const int E = in_sizes[1] / 2;   // 4032 = 64*63 (dense permutations)

    kA<<<BN / 8, 256>>>(x, Wg, bg, W1, b1, Wgcn, bgcn, Wp, bp, out);
    k1<<<Bc * 16, 256>>>(W2, b2, out, E);
}

// round 4
// speedup vs baseline: 2.0964x; 1.2166x over previous
#include <cuda_runtime.h>

// Problem constants (STGNN_91242285236402): B=8, T=16, N=64, F=16, H=128
#define Bc 8
#define Tc 16
#define Nc 64
#define Fc 16
#define Hc 128
#define BN (Bc * Nc)   // 512
#define PADN 68        // padded row width for bt_sh [k][t]
#define GRID 128

// Scratch (allocation-free: __device__ globals)
__device__ float g_a  [BN * Hc];        // a[row][k]   = node@W1s.T + b1
__device__ float g_btT[Bc * Hc * Nc];   // btT[b][k][n] = (node@W1t.T) transposed
__device__ float g_lp [BN];             // Wp . (Wgcn@node + bgcn)
__device__ unsigned g_bar = 0;          // grid barrier (monotonic, replay-safe)

union SmemU {
    struct {
        float x[8][Fc];
        float node[8][Hc];
        float wv2[2][Hc];
        float cb;
    } A;
    struct {
        float bt[Hc][PADN];   // 34.8 KB
        float a[4][Hc];
        float w2[Hc];
        float lp[4];
        float pr[Nc];
    } B;
};

__device__ __forceinline__ void grid_bar()
{
    __syncthreads();
    __threadfence();
    if (threadIdx.x == 0) {
        unsigned v = atomicAdd(&g_bar, 1u);
        unsigned target = (v & ~(GRID - 1u)) + GRID;   // end of this launch's wave
        volatile unsigned* p = &g_bar;
        while (*p < target) { }
        __threadfence();
    }
    __syncthreads();
}

// ---------------------------------------------------------------------------
// Fused kernel, 128 blocks x 256 threads.
// Phase A: block = (rowgroup 0..63  = blockIdx>>1, bh = blockIdx&1).
//   bh=0: a[k] = b1[k] + node.W1s[k]; also wvec/cb/lp/pressure-init.
//   bh=1: btT[b][k][n] = node.W1t[k].
// Phase B: block = (b = blockIdx>>4, src-group g = blockIdx&15); dense edges:
//   ew(s,t) = b2 + sum_k relu(a[s,k] + btT[k,t]) * W2[k],  e = s*63 + (t-(t>s))
//   pressures[b,t] += ew * lp[s]
// ---------------------------------------------------------------------------
__global__ void __launch_bounds__(256) kfused(
    const float* __restrict__ x,   const float* __restrict__ Wg,
    const float* __restrict__ bg,  const float* __restrict__ W1,
    const float* __restrict__ b1,  const float* __restrict__ W2,
    const float* __restrict__ b2,  const float* __restrict__ Wgcn,
    const float* __restrict__ bgcn,const float* __restrict__ Wp,
    const float* __restrict__ bp,  float* __restrict__ out, int E)
{
    __shared__ SmemU sm;
    const int tid = threadIdx.x;

    // ================= Phase A =================
    {
        const int bh = blockIdx.x & 1;          // 0 -> a, 1 -> btT
        const int rowbase = (blockIdx.x >> 1) * 8;
        const int t    = tid & (Hc - 1);
        const int half = tid >> 7;

        // stage x (8 rows x 16 f)
        if (tid < 128) {
            int r = tid >> 4, f = tid & 15;
            int row = rowbase + r, b = row >> 6, n = row & 63;
            sm.A.x[r][f] = x[(((b * Tc + (Tc - 1)) * Nc + n) * Fc) + f];
        }

        if (bh == 0) {
            if (tid < 8) out[rowbase + tid] = __ldg(bp);   // pressures init
            // wvec halves: coalesced Wgcn rows
            float s = 0.f;
            const int k0 = half * 64;
            #pragma unroll 16
            for (int k = 0; k < 64; k++)
                s += __ldg(&Wp[k0 + k]) * __ldg(&Wgcn[(k0 + k) * Hc + t]);
            sm.A.wv2[half][t] = s;
            if (tid == 0) sm.A.cb = 0.f;
        }
        __syncthreads();

        if (bh == 0 && tid < 128) {
            float v = __ldg(&Wp[t]) * __ldg(&bgcn[t]);
            #pragma unroll
            for (int o = 16; o; o >>= 1) v += __shfl_xor_sync(0xffffffffu, v, o);
            if ((tid & 31) == 0) atomicAdd(&sm.A.cb, v);
        }

        // node: 8 rows x 128 h over 256 threads
        #pragma unroll
        for (int i = 0; i < 4; i++) {
            int idx = tid + i * 256;
            int r = idx >> 7, h = idx & 127;
            const float4* wg4 = (const float4*)(Wg + h * Fc);
            float4 w0 = __ldg(wg4 + 0), w1 = __ldg(wg4 + 1);
            float4 w2 = __ldg(wg4 + 2), w3 = __ldg(wg4 + 3);
            const float* xr = sm.A.x[r];
            float acc = __ldg(&bg[h]);
            acc += xr[0]*w0.x + xr[1]*w0.y + xr[2]*w0.z + xr[3]*w0.w;
            acc += xr[4]*w1.x + xr[5]*w1.y + xr[6]*w1.z + xr[7]*w1.w;
            acc += xr[8]*w2.x + xr[9]*w2.y + xr[10]*w2.z + xr[11]*w2.w;
            acc += xr[12]*w3.x + xr[13]*w3.y + xr[14]*w3.z + xr[15]*w3.w;
            sm.A.node[r][h] = acc;
        }
        __syncthreads();

        // GEMM: warp w covers k in [w*16, w*16+16); 8-lane dots (j), d picks k.
        const int lane = tid & 31, w = tid >> 5;
        const int j = lane & 7, d = lane >> 3;
        const float* Wbase = W1 + bh * Hc;

        #pragma unroll
        for (int r = 0; r < 8; r++) {
            const float* nrow = &sm.A.node[r][j * 16];
            float4 n0 = *(const float4*)(nrow + 0);
            float4 n1 = *(const float4*)(nrow + 4);
            float4 n2 = *(const float4*)(nrow + 8);
            float4 n3 = *(const float4*)(nrow + 12);
            #pragma unroll
            for (int kk = 0; kk < 4; kk++) {
                int k = w * 16 + kk * 4 + d;
                const float4* wp4 = (const float4*)(Wbase + k * (2 * Hc) + j * 16);
                float4 w0 = __ldg(wp4 + 0), w1 = __ldg(wp4 + 1);
                float4 w2 = __ldg(wp4 + 2), w3 = __ldg(wp4 + 3);
                float acc = n0.x*w0.x + n0.y*w0.y + n0.z*w0.z + n0.w*w0.w
                          + n1.x*w1.x + n1.y*w1.y + n1.z*w1.z + n1.w*w1.w
                          + n2.x*w2.x + n2.y*w2.y + n2.z*w2.z + n2.w*w2.w
                          + n3.x*w3.x + n3.y*w3.y + n3.z*w3.z + n3.w*w3.w;
                acc += __shfl_xor_sync(0xffffffffu, acc, 1);
                acc += __shfl_xor_sync(0xffffffffu, acc, 2);
                acc += __shfl_xor_sync(0xffffffffu, acc, 4);
                if (j == 0) {
                    int row = rowbase + r;
                    if (bh == 0) {
                        g_a[row * Hc + k] = acc + __ldg(&b1[k]);
                    } else {
                        int b = row >> 6, n = row & 63;
                        g_btT[(b * Hc + k) * Nc + n] = acc;
                    }
                }
            }
        }

        // lp: warp w reduces row w (only a-blocks)
        if (bh == 0) {
            float4 n  = *(const float4*)&sm.A.node[w][lane * 4];
            float4 wa = *(const float4*)&sm.A.wv2[0][lane * 4];
            float4 wb = *(const float4*)&sm.A.wv2[1][lane * 4];
            float v = n.x*(wa.x+wb.x) + n.y*(wa.y+wb.y)
                    + n.z*(wa.z+wb.z) + n.w*(wa.w+wb.w);
            #pragma unroll
            for (int o = 16; o; o >>= 1) v += __shfl_xor_sync(0xffffffffu, v, o);
            if (lane == 0) g_lp[rowbase + w] = v + sm.A.cb;
        }
    }

    // ================= grid barrier =================
    grid_bar();

    // ================= Phase B =================
    {
        const int b = blockIdx.x >> 4;
        const int g = blockIdx.x & 15;

        // stage btT[b] (128 x 64 floats) transposed-padded
        const float4* src4 = (const float4*)(g_btT + b * Hc * Nc);
        #pragma unroll
        for (int p = 0; p < 8; p++) {
            int q = tid + p * 256;          // quad index 0..2047
            int k = q >> 4, t4 = q & 15;
            float4 v = __ldg(src4 + q);
            *(float4*)&sm.B.bt[k][t4 * 4] = v;
        }
        if (tid < 128) {
            int sl = tid >> 5, k4 = tid & 31;
            *(float4*)&sm.B.a[sl][k4 * 4] =
                __ldg((const float4*)(g_a + (b * Nc + g * 4 + sl) * Hc) + k4);
            sm.B.w2[tid] = __ldg(&W2[tid]);
        }
        if (tid < 4)  sm.B.lp[tid] = g_lp[b * Nc + g * 4 + tid];
        if (tid < Nc) sm.B.pr[tid] = 0.f;
        __syncthreads();

        const int w = tid >> 5, lane = tid & 31;
        const int sl = w >> 1;
        const int t  = (w & 1) * 32 + lane;
        const int s  = g * 4 + sl;

        float acc = 0.f;
        #pragma unroll 8
        for (int kq = 0; kq < 32; kq++) {
            float4 a4 = *(const float4*)&sm.B.a[sl][kq * 4];
            float4 w4 = *(const float4*)&sm.B.w2[kq * 4];
            float b0 = sm.B.bt[kq * 4 + 0][t];
            float b1v= sm.B.bt[kq * 4 + 1][t];
            float b2v= sm.B.bt[kq * 4 + 2][t];
            float b3 = sm.B.bt[kq * 4 + 3][t];
            acc += fmaxf(a4.x + b0, 0.f) * w4.x;
            acc += fmaxf(a4.y + b1v,0.f) * w4.y;
            acc += fmaxf(a4.z + b2v,0.f) * w4.z;
            acc += fmaxf(a4.w + b3, 0.f) * w4.w;
        }

        if (t != s) {
            float ew = acc + __ldg(b2);
            int e = s * 63 + (t < s ? t : t - 1);
            out[BN + b * E + e] = ew;
            atomicAdd(&sm.B.pr[t], ew * sm.B.lp[sl]);
        }
        __syncthreads();
        if (tid < Nc) atomicAdd(out + b * Nc + tid, sm.B.pr[tid]);
    }
}

// ---------------------------------------------------------------------------
extern "C" void kernel_launch(void* const* d_in, const int* in_sizes, int n_in,
                              void* d_out, int out_size)
{
    const float* x    = (const float*)d_in[0];
    const float* Wg   = (const float*)d_in[2];
    const float* bg   = (const float*)d_in[3];
    const float* W1   = (const float*)d_in[4];
    const float* b1   = (const float*)d_in[5];
    const float* W2   = (const float*)d_in[6];
    const float* b2   = (const float*)d_in[7];
    const float* Wgcn = (const float*)d_in[8];
    const float* bgcn = (const float*)d_in[9];
    const float* Wp   = (const float*)d_in[14];
    const float* bp   = (const float*)d_in[15];
    float* out = (float*)d_out;

    const int E = in_sizes[1] / 2;   // 4032 = 64*63 (dense permutations)

    kfused<<<GRID, 256>>>(x, Wg, bg, W1, b1, W2, b2,
                          Wgcn, bgcn, Wp, bp, out, E);
}